// round 5
// baseline (speedup 1.0000x reference)
#include <cuda_runtime.h>
#include <cuda_bf16.h>
#include <cstdint>

#define DVAL 64
#define MAXM 16384
#define MAXN 8192
#define REGP   0.05f
#define LOG2E  1.4426950408889634f
#define LN2    0.6931471805599453f
#define SHIFT  28.0f

#define THREADS 512          // 16 warps
#define BLOCK_ROWS 512       // 32 rows per warp
#define TJ 128               // j-tile
#define JSPLIT 9
#define STAGE 16896          // 16384 tile + 512 bias

__device__ double g_cost_sum;
__device__ double g_psi_sum;
__device__ double g_result;
__device__ unsigned int g_done;
__device__ float  g_sqt[MAXM];
__device__ float  g_sqs[MAXN];
__device__ float  g_bias[MAXM];
__device__ float  g_rowsum[MAXN];
__device__ uint32_t g_tgtb[MAXM * DVAL / 2];   // bf16x2 packed
__device__ uint32_t g_srcb[MAXN * DVAL / 2];

// ---------- helpers ----------
static __device__ __forceinline__ unsigned long long pack2(float a, float b) {
    unsigned long long r; asm("mov.b64 %0, {%1, %2};" : "=l"(r) : "f"(a), "f"(b)); return r;
}
static __device__ __forceinline__ unsigned long long pack2r(uint32_t a, uint32_t b) {
    unsigned long long r; asm("mov.b64 %0, {%1, %2};" : "=l"(r) : "r"(a), "r"(b)); return r;
}
static __device__ __forceinline__ unsigned long long ffma2(unsigned long long a, unsigned long long b, unsigned long long c) {
    unsigned long long d; asm("fma.rn.f32x2 %0, %1, %2, %3;" : "=l"(d) : "l"(a), "l"(b), "l"(c)); return d;
}
static __device__ __forceinline__ unsigned long long fadd2(unsigned long long a, unsigned long long b) {
    unsigned long long d; asm("add.rn.f32x2 %0, %1, %2;" : "=l"(d) : "l"(a), "l"(b)); return d;
}
static __device__ __forceinline__ float unpack_sum(unsigned long long a) {
    float lo, hi; asm("mov.b64 {%0, %1}, %2;" : "=f"(lo), "=f"(hi) : "l"(a)); return lo + hi;
}
static __device__ __forceinline__ void unpack2(unsigned long long a, float& lo, float& hi) {
    asm("mov.b64 {%0, %1}, %2;" : "=f"(lo), "=f"(hi) : "l"(a));
}
static __device__ __forceinline__ uint32_t cvt_bf16x2(float lo, float hi) {
    uint32_t r; asm("cvt.rn.bf16x2.f32 %0, %1, %2;" : "=r"(r) : "f"(hi), "f"(lo)); return r;
}
static __device__ __forceinline__ uint32_t ex2_bf16x2(uint32_t a) {
    uint32_t r; asm("ex2.approx.ftz.bf16x2 %0, %1;" : "=r"(r) : "r"(a)); return r;
}
static __device__ __forceinline__ void mma16816(float* c, const uint32_t* a, uint32_t b0, uint32_t b1) {
    asm("mma.sync.aligned.m16n8k16.row.col.f32.bf16.bf16.f32 "
        "{%0,%1,%2,%3}, {%4,%5,%6,%7}, {%8,%9}, {%0,%1,%2,%3};"
        : "+f"(c[0]), "+f"(c[1]), "+f"(c[2]), "+f"(c[3])
        : "r"(a[0]), "r"(a[1]), "r"(a[2]), "r"(a[3]), "r"(b0), "r"(b1));
}
static __device__ __forceinline__ uint32_t smem_u32(const void* p) {
    uint32_t a;
    asm("{ .reg .u64 t; cvta.to.shared.u64 t, %1; cvt.u32.u64 %0, t; }" : "=r"(a) : "l"(p));
    return a;
}
#define CP_ASYNC16(dst, src) \
    asm volatile("cp.async.cg.shared.global [%0], [%1], 16;" :: "r"(dst), "l"(src) : "memory")
#define CP_COMMIT() asm volatile("cp.async.commit_group;" ::: "memory")
#define CP_WAIT0()  asm volatile("cp.async.wait_group 0;" ::: "memory")

// ---------------- kernel 1: convert + reductions + init ----------------
__global__ void k_pre(const float* __restrict__ src, const float* __restrict__ tgt,
                      const float* __restrict__ psi, int N, int M) {
    int gtid = blockIdx.x * blockDim.x + threadIdx.x;
    int nth  = gridDim.x * blockDim.x;
    int lane = threadIdx.x & 31;

    if (gtid == 0) { g_cost_sum = 0.0; g_psi_sum = 0.0; g_result = 0.0; g_done = 0u; }
    for (int i = gtid; i < N; i += nth) g_rowsum[i] = 0.0f;

    // convert tgt -> bf16x2 while accumulating total |y|^2 (coalesced)
    const float2* t2 = (const float2*)tgt;
    float cs = 0.0f;
    for (int i = gtid; i < M * 32; i += nth) {
        float2 v = t2[i];
        cs += v.x * v.x + v.y * v.y;
        g_tgtb[i] = cvt_bf16x2(v.x, v.y);
    }
    // convert src -> bf16x2
    const float2* s2 = (const float2*)src;
    for (int i = gtid; i < N * 32; i += nth) {
        float2 v = s2[i];
        g_srcb[i] = cvt_bf16x2(v.x, v.y);
    }
    // psi sum (coalesced)
    float pp = 0.0f;
    for (int i = gtid; i < M; i += nth) pp += psi[i];
    #pragma unroll
    for (int o = 16; o; o >>= 1) {
        cs += __shfl_xor_sync(0xffffffffu, cs, o);
        pp += __shfl_xor_sync(0xffffffffu, pp, o);
    }
    if (lane == 0) {
        atomicAdd(&g_cost_sum, (double)cs);
        if (pp != 0.0f) atomicAdd(&g_psi_sum, (double)pp);
    }

    // per-row squared norms (tgt rows then src rows), 4 lanes per row
    int grp = gtid >> 2, sub = gtid & 3, ngrp = nth >> 2;
    for (int row = grp; row < M + N; row += ngrp) {
        const float4* p = (row < M)
            ? (const float4*)(tgt + (size_t)row * DVAL)
            : (const float4*)(src + (size_t)(row - M) * DVAL);
        float s = 0.0f;
        #pragma unroll
        for (int q = 0; q < 4; ++q) {
            float4 v = p[sub + q * 4];
            s += v.x * v.x + v.y * v.y + v.z * v.z + v.w * v.w;
        }
        s += __shfl_xor_sync(0xffffffffu, s, 1);
        s += __shfl_xor_sync(0xffffffffu, s, 2);
        if (sub == 0) {
            if (row < M) g_sqt[row] = s; else g_sqs[row - M] = s;
        }
    }
}

// ---------------- kernel 2: bias precompute ----------------
__global__ void k_prep(const float* __restrict__ psi, int M) {
    int j = blockIdx.x * blockDim.x + threadIdx.x;
    if (j >= M) return;
    float cn    = (float)(g_cost_sum / (double)M);
    float alpha = 1.0f / (REGP * cn);
    g_bias[j] = LOG2E * (psi[j] * (1.0f / REGP) - alpha * g_sqt[j]) + SHIFT;
}

// ---------------- kernel 3: main HMMA + bf16x2 exp2 ----------------
__global__ void __launch_bounds__(THREADS, 1)
k_main_mma(int N, int M) {
    __shared__ char sm[2 * STAGE];
    const uint32_t smb = smem_u32(sm);

    const int tid  = threadIdx.x;
    const int wid  = tid >> 5;
    const int lane = tid & 31;
    const int g    = lane >> 2;
    const int kp   = (lane & 3) * 2;

    const int rbase = blockIdx.x * BLOCK_ROWS + wid * 32;

    // ---- A fragments from bf16 globals ----
    uint32_t afr[2][4][4];
    {
        const uint32_t* xb = g_srcb + (size_t)rbase * 32;
        #pragma unroll
        for (int t = 0; t < 2; ++t) {
            #pragma unroll
            for (int ks = 0; ks < 4; ++ks) {
                const uint32_t* p = xb + (t * 16 + g) * 32 + ks * 8 + (kp >> 1);
                afr[t][ks][0] = p[0];
                afr[t][ks][1] = p[256];
                afr[t][ks][2] = p[4];
                afr[t][ks][3] = p[260];
            }
        }
    }

    const float cn = (float)(g_cost_sum / (double)M);
    const float k1 = 2.0f * LOG2E / (REGP * cn);
    const unsigned long long k1p = pack2(k1, k1);

    const int nb = g * 128;
    int kx[4][2];
    #pragma unroll
    for (int ks = 0; ks < 4; ++ks) {
        int base = ks * 32 + (lane & 3) * 4;
        kx[ks][0] = (base)      ^ (g << 4);
        kx[ks][1] = (base + 16) ^ (g << 4);
    }
    const int biasoff = (lane & 3) * 2;

    const int TT = M / TJ;
    const int tbeg = (blockIdx.y * TT) / JSPLIT;
    const int tend = ((blockIdx.y + 1) * TT) / JSPLIT;

    const int ch0 = tid,       r0 = ch0 >> 3, c0 = ch0 & 7;
    const int ch1 = tid + 512, r1 = ch1 >> 3, c1 = ch1 & 7;
    const uint32_t d0 = (uint32_t)((r0 * 128 + c0 * 16) ^ ((r0 & 7) << 4));
    const uint32_t d1 = (uint32_t)((r1 * 128 + c1 * 16) ^ ((r1 & 7) << 4));
    const char* tgtb_bytes = (const char*)g_tgtb;
    const char* bias_bytes = (const char*)g_bias;

    // ---- prologue: fill stage 0 ----
    {
        int j0 = tbeg * TJ;
        CP_ASYNC16(smb + d0, tgtb_bytes + (size_t)(j0 + r0) * 128 + c0 * 16);
        CP_ASYNC16(smb + d1, tgtb_bytes + (size_t)(j0 + r1) * 128 + c1 * 16);
        if (tid < 32) CP_ASYNC16(smb + 16384 + tid * 16, bias_bytes + (size_t)j0 * 4 + tid * 16);
        CP_COMMIT();
    }

    unsigned long long rs[4] = {0ull, 0ull, 0ull, 0ull};

    for (int t = tbeg; t < tend; ++t) {
        const int cur = (t - tbeg) & 1, nxt = cur ^ 1;
        const bool more = (t + 1 < tend);

        CP_WAIT0();
        __syncthreads();

        if (more) {
            int j0 = (t + 1) * TJ;
            uint32_t dst = smb + (uint32_t)(nxt * STAGE);
            CP_ASYNC16(dst + d0, tgtb_bytes + (size_t)(j0 + r0) * 128 + c0 * 16);
            CP_ASYNC16(dst + d1, tgtb_bytes + (size_t)(j0 + r1) * 128 + c1 * 16);
            if (tid < 32) CP_ASYNC16(dst + 16384 + tid * 16, bias_bytes + (size_t)j0 * 4 + tid * 16);
            CP_COMMIT();
        }

        const char* tb = sm + cur * STAGE;
        const float* bb = (const float*)(tb + 16384);
        #pragma unroll 4
        for (int s = 0; s < 16; ++s) {
            float c0f[4] = {0.f, 0.f, 0.f, 0.f};
            float c1f[4] = {0.f, 0.f, 0.f, 0.f};
            const char* sbase = tb + s * 1024 + nb;
            #pragma unroll
            for (int ks = 0; ks < 4; ++ks) {
                uint32_t b0 = *(const uint32_t*)(sbase + kx[ks][0]);
                uint32_t b1 = *(const uint32_t*)(sbase + kx[ks][1]);
                mma16816(c0f, afr[0][ks], b0, b1);
                mma16816(c1f, afr[1][ks], b0, b1);
            }
            unsigned long long biasp = *(const unsigned long long*)(bb + s * 8 + biasoff);
            unsigned long long a01 = ffma2(pack2(c0f[0], c0f[1]), k1p, biasp);
            unsigned long long a23 = ffma2(pack2(c0f[2], c0f[3]), k1p, biasp);
            unsigned long long a45 = ffma2(pack2(c1f[0], c1f[1]), k1p, biasp);
            unsigned long long a67 = ffma2(pack2(c1f[2], c1f[3]), k1p, biasp);
            float x0, x1; unpack2(a01, x0, x1);
            float x2, x3; unpack2(a23, x2, x3);
            float x4, x5; unpack2(a45, x4, x5);
            float x6, x7; unpack2(a67, x6, x7);
            uint32_t e0 = ex2_bf16x2(cvt_bf16x2(x0, x1));
            uint32_t e1 = ex2_bf16x2(cvt_bf16x2(x2, x3));
            uint32_t e2 = ex2_bf16x2(cvt_bf16x2(x4, x5));
            uint32_t e3 = ex2_bf16x2(cvt_bf16x2(x6, x7));
            rs[0] = fadd2(rs[0], pack2r(e0 << 16, e0 & 0xFFFF0000u));
            rs[1] = fadd2(rs[1], pack2r(e1 << 16, e1 & 0xFFFF0000u));
            rs[2] = fadd2(rs[2], pack2r(e2 << 16, e2 & 0xFFFF0000u));
            rs[3] = fadd2(rs[3], pack2r(e3 << 16, e3 & 0xFFFF0000u));
        }
        __syncthreads();
    }

    const int rows[4] = { rbase + g, rbase + 8 + g, rbase + 16 + g, rbase + 24 + g };
    #pragma unroll
    for (int q = 0; q < 4; ++q) {
        float s = unpack_sum(rs[q]);
        s += __shfl_xor_sync(0xffffffffu, s, 1);
        s += __shfl_xor_sync(0xffffffffu, s, 2);
        if ((lane & 3) == 0) atomicAdd(&g_rowsum[rows[q]], s);
    }
}

// ---------------- kernel 4: finalize ----------------
__global__ void k_final(float* out, int N, int M, int nblocks) {
    int i = blockIdx.x * blockDim.x + threadIdx.x;
    int lane = threadIdx.x & 31;
    float part = 0.0f;
    if (i < N) {
        float cn    = (float)(g_cost_sum / (double)M);
        float alpha = 1.0f / (REGP * cn);
        float log_nu = -logf((float)M);
        float lse = -alpha * g_sqs[i] + log_nu + LN2 * (log2f(g_rowsum[i]) - SHIFT);
        part = -REGP * lse / (float)N;
    }
    #pragma unroll
    for (int o = 16; o; o >>= 1) part += __shfl_xor_sync(0xffffffffu, part, o);
    if (lane == 0) atomicAdd(&g_result, (double)part);
    __syncthreads();
    if (threadIdx.x == 0) {
        __threadfence();
        unsigned int old = atomicAdd(&g_done, 1u);
        if (old == (unsigned int)(nblocks - 1)) {
            out[0] = (float)(g_result + g_psi_sum / (double)M);
        }
    }
}

extern "C" void kernel_launch(void* const* d_in, const int* in_sizes, int n_in,
                              void* d_out, int out_size) {
    const float* src = (const float*)d_in[0];   // [N, 64]
    const float* tgt = (const float*)d_in[1];   // [M, 64]
    const float* psi = (const float*)d_in[2];   // [M]
    int N = in_sizes[0] / DVAL;
    int M = in_sizes[2];

    k_pre<<<192, 256>>>(src, tgt, psi, N, M);
    k_prep<<<(M + 255) / 256, 256>>>(psi, M);

    dim3 grd(N / BLOCK_ROWS, JSPLIT);           // 16 x 9 = 144 CTAs
    k_main_mma<<<grd, THREADS>>>(N, M);

    int fb = (N + 255) / 256;                   // 32 blocks
    k_final<<<fb, 256>>>((float*)d_out, N, M, fb);
}

// round 6
// speedup vs baseline: 1.4279x; 1.4279x over previous
#include <cuda_runtime.h>
#include <cuda_bf16.h>
#include <cstdint>

#define DVAL 64
#define MAXM 16384
#define MAXN 8192
#define REGP   0.05f
#define LOG2E  1.4426950408889634f
#define LN2    0.6931471805599453f
#define SHIFT  28.0f

#define THREADS 512          // 16 warps
#define BLOCK_ROWS 512       // 32 rows per warp
#define TJ 128               // j-tile
#define JSPLIT 9
#define MAXTILES 15          // ceil(128/9)

__device__ double g_cost_sum;
__device__ double g_psi_sum;
__device__ double g_result;
__device__ unsigned int g_done;
__device__ float  g_sqt[MAXM];
__device__ float  g_sqs[MAXN];
__device__ float  g_rowsum[MAXN];
__device__ uint32_t g_tgtb[MAXM * DVAL / 2];   // bf16x2 packed
__device__ uint32_t g_srcb[MAXN * DVAL / 2];

// ---------- helpers ----------
static __device__ __forceinline__ unsigned long long pack2(float a, float b) {
    unsigned long long r; asm("mov.b64 %0, {%1, %2};" : "=l"(r) : "f"(a), "f"(b)); return r;
}
static __device__ __forceinline__ unsigned long long pack2r(uint32_t a, uint32_t b) {
    unsigned long long r; asm("mov.b64 %0, {%1, %2};" : "=l"(r) : "r"(a), "r"(b)); return r;
}
static __device__ __forceinline__ unsigned long long ffma2(unsigned long long a, unsigned long long b, unsigned long long c) {
    unsigned long long d; asm("fma.rn.f32x2 %0, %1, %2, %3;" : "=l"(d) : "l"(a), "l"(b), "l"(c)); return d;
}
static __device__ __forceinline__ unsigned long long fadd2(unsigned long long a, unsigned long long b) {
    unsigned long long d; asm("add.rn.f32x2 %0, %1, %2;" : "=l"(d) : "l"(a), "l"(b)); return d;
}
static __device__ __forceinline__ float unpack_sum(unsigned long long a) {
    float lo, hi; asm("mov.b64 {%0, %1}, %2;" : "=f"(lo), "=f"(hi) : "l"(a)); return lo + hi;
}
static __device__ __forceinline__ void unpack2(unsigned long long a, float& lo, float& hi) {
    asm("mov.b64 {%0, %1}, %2;" : "=f"(lo), "=f"(hi) : "l"(a));
}
static __device__ __forceinline__ uint32_t cvt_bf16x2(float lo, float hi) {
    uint32_t r; asm("cvt.rn.bf16x2.f32 %0, %1, %2;" : "=r"(r) : "f"(hi), "f"(lo)); return r;
}
static __device__ __forceinline__ uint32_t ex2_bf16x2(uint32_t a) {
    uint32_t r; asm("ex2.approx.ftz.bf16x2 %0, %1;" : "=r"(r) : "r"(a)); return r;
}
static __device__ __forceinline__ void mma16816(float* c, const uint32_t* a, uint32_t b0, uint32_t b1) {
    asm("mma.sync.aligned.m16n8k16.row.col.f32.bf16.bf16.f32 "
        "{%0,%1,%2,%3}, {%4,%5,%6,%7}, {%8,%9}, {%0,%1,%2,%3};"
        : "+f"(c[0]), "+f"(c[1]), "+f"(c[2]), "+f"(c[3])
        : "r"(a[0]), "r"(a[1]), "r"(a[2]), "r"(a[3]), "r"(b0), "r"(b1));
}
static __device__ __forceinline__ void ldm_x4(uint32_t* r, uint32_t addr) {
    asm volatile("ldmatrix.sync.aligned.m8n8.x4.shared.b16 {%0,%1,%2,%3}, [%4];"
        : "=r"(r[0]), "=r"(r[1]), "=r"(r[2]), "=r"(r[3]) : "r"(addr));
}
static __device__ __forceinline__ uint32_t smem_u32(const void* p) {
    uint32_t a;
    asm("{ .reg .u64 t; cvta.to.shared.u64 t, %1; cvt.u32.u64 %0, t; }" : "=r"(a) : "l"(p));
    return a;
}
#define CP_ASYNC16(dst, src) \
    asm volatile("cp.async.cg.shared.global [%0], [%1], 16;" :: "r"(dst), "l"(src) : "memory")
#define CP_COMMIT() asm volatile("cp.async.commit_group;" ::: "memory")
#define CP_WAIT0()  asm volatile("cp.async.wait_group 0;" ::: "memory")

// ---------------- kernel 1: convert + reductions + init ----------------
__global__ void k_pre(const float* __restrict__ src, const float* __restrict__ tgt,
                      const float* __restrict__ psi, int N, int M) {
    int gtid = blockIdx.x * blockDim.x + threadIdx.x;
    int nth  = gridDim.x * blockDim.x;
    int lane = threadIdx.x & 31;

    if (gtid == 0) { g_cost_sum = 0.0; g_psi_sum = 0.0; g_result = 0.0; g_done = 0u; }
    for (int i = gtid; i < N; i += nth) g_rowsum[i] = 0.0f;

    const float2* t2 = (const float2*)tgt;
    float cs = 0.0f;
    for (int i = gtid; i < M * 32; i += nth) {
        float2 v = t2[i];
        cs += v.x * v.x + v.y * v.y;
        g_tgtb[i] = cvt_bf16x2(v.x, v.y);
    }
    const float2* s2 = (const float2*)src;
    for (int i = gtid; i < N * 32; i += nth) {
        float2 v = s2[i];
        g_srcb[i] = cvt_bf16x2(v.x, v.y);
    }
    float pp = 0.0f;
    for (int i = gtid; i < M; i += nth) pp += psi[i];
    #pragma unroll
    for (int o = 16; o; o >>= 1) {
        cs += __shfl_xor_sync(0xffffffffu, cs, o);
        pp += __shfl_xor_sync(0xffffffffu, pp, o);
    }
    if (lane == 0) {
        atomicAdd(&g_cost_sum, (double)cs);
        if (pp != 0.0f) atomicAdd(&g_psi_sum, (double)pp);
    }

    // per-row squared norms, 4 lanes per row
    int grp = gtid >> 2, sub = gtid & 3, ngrp = nth >> 2;
    for (int row = grp; row < M + N; row += ngrp) {
        const float4* p = (row < M)
            ? (const float4*)(tgt + (size_t)row * DVAL)
            : (const float4*)(src + (size_t)(row - M) * DVAL);
        float s = 0.0f;
        #pragma unroll
        for (int q = 0; q < 4; ++q) {
            float4 v = p[sub + q * 4];
            s += v.x * v.x + v.y * v.y + v.z * v.z + v.w * v.w;
        }
        s += __shfl_xor_sync(0xffffffffu, s, 1);
        s += __shfl_xor_sync(0xffffffffu, s, 2);
        if (sub == 0) {
            if (row < M) g_sqt[row] = s; else g_sqs[row - M] = s;
        }
    }
}

// ---------------- kernel 2: main HMMA + bf16x2 exp2 + inline finalize ----------------
__global__ void __launch_bounds__(THREADS, 1)
k_main_mma(const float* __restrict__ psi, float* __restrict__ out, int N, int M) {
    __shared__ char sm[2 * 16384 + MAXTILES * TJ * 4];
    __shared__ int smflag;
    float* sbias = (float*)(sm + 32768);
    const uint32_t smb = smem_u32(sm);

    const int tid  = threadIdx.x;
    const int wid  = tid >> 5;
    const int lane = tid & 31;
    const int g    = lane >> 2;

    const int rbase = blockIdx.x * BLOCK_ROWS + wid * 32;

    const int TT = M / TJ;
    const int tbeg = (blockIdx.y * TT) / JSPLIT;
    const int tend = ((blockIdx.y + 1) * TT) / JSPLIT;
    const int jbase = tbeg * TJ;
    const int jcnt  = (tend - tbeg) * TJ;

    // per-thread cp.async chunk coords
    const int ch0 = tid,       r0 = ch0 >> 3, c0 = ch0 & 7;
    const int ch1 = tid + 512, r1 = ch1 >> 3, c1 = ch1 & 7;
    const uint32_t d0 = (uint32_t)((r0 * 128 + c0 * 16) ^ ((r0 & 7) << 4));
    const uint32_t d1 = (uint32_t)((r1 * 128 + c1 * 16) ^ ((r1 & 7) << 4));
    const char* tgtb_bytes = (const char*)g_tgtb;

    // ---- start tile 0 fill ----
    CP_ASYNC16(smb + d0, tgtb_bytes + (size_t)(jbase + r0) * 128 + c0 * 16);
    CP_ASYNC16(smb + d1, tgtb_bytes + (size_t)(jbase + r1) * 128 + c1 * 16);
    CP_COMMIT();

    const float cn = (float)(g_cost_sum / (double)M);
    const float alpha = 1.0f / (REGP * cn);
    const float k1 = 2.0f * LOG2E * alpha;
    const unsigned long long k1p = pack2(k1, k1);

    // ---- bias for whole j-range into smem (overlaps cp.async) ----
    for (int jj = tid; jj < jcnt; jj += THREADS) {
        int j = jbase + jj;
        sbias[jj] = LOG2E * (psi[j] * (1.0f / REGP) - alpha * g_sqt[j]) + SHIFT;
    }

    // ---- A fragments from bf16 globals ----
    uint32_t afr[2][4][4];
    {
        const uint32_t* xb = g_srcb + (size_t)rbase * 32;
        #pragma unroll
        for (int t = 0; t < 2; ++t) {
            #pragma unroll
            for (int ks = 0; ks < 4; ++ks) {
                const uint32_t* p = xb + (t * 16 + g) * 32 + ks * 8 + (lane & 3);
                afr[t][ks][0] = p[0];
                afr[t][ks][1] = p[256];
                afr[t][ks][2] = p[4];
                afr[t][ks][3] = p[260];
            }
        }
    }

    // ldmatrix per-lane addresses (s-invariant swizzle)
    const int lr = lane & 7, lq = lane >> 3;
    const uint32_t lmoff0 = (uint32_t)(lr * 128 + ((lq * 16)       ^ (lr << 4)));
    const uint32_t lmoff1 = (uint32_t)(lr * 128 + (((lq + 4) * 16) ^ (lr << 4)));
    const int biasoff = (lane & 3) * 2;

    unsigned long long rs[4] = {0ull, 0ull, 0ull, 0ull};

    for (int t = tbeg; t < tend; ++t) {
        const int cur = (t - tbeg) & 1, nxt = cur ^ 1;
        const bool more = (t + 1 < tend);

        CP_WAIT0();
        __syncthreads();

        if (more) {
            int j0 = (t + 1) * TJ;
            uint32_t dst = smb + (uint32_t)(nxt * 16384);
            CP_ASYNC16(dst + d0, tgtb_bytes + (size_t)(j0 + r0) * 128 + c0 * 16);
            CP_ASYNC16(dst + d1, tgtb_bytes + (size_t)(j0 + r1) * 128 + c1 * 16);
            CP_COMMIT();
        }

        const uint32_t tadd = smb + (uint32_t)(cur * 16384);
        const float* bb = sbias + (t - tbeg) * TJ;
        #pragma unroll 4
        for (int s = 0; s < 16; ++s) {
            float c0f[4] = {0.f, 0.f, 0.f, 0.f};
            float c1f[4] = {0.f, 0.f, 0.f, 0.f};
            uint32_t bA[4], bB[4];
            ldm_x4(bA, tadd + s * 1024 + lmoff0);
            ldm_x4(bB, tadd + s * 1024 + lmoff1);
            mma16816(c0f, afr[0][0], bA[0], bA[1]);
            mma16816(c1f, afr[1][0], bA[0], bA[1]);
            mma16816(c0f, afr[0][1], bA[2], bA[3]);
            mma16816(c1f, afr[1][1], bA[2], bA[3]);
            mma16816(c0f, afr[0][2], bB[0], bB[1]);
            mma16816(c1f, afr[1][2], bB[0], bB[1]);
            mma16816(c0f, afr[0][3], bB[2], bB[3]);
            mma16816(c1f, afr[1][3], bB[2], bB[3]);

            unsigned long long biasp = *(const unsigned long long*)(bb + s * 8 + biasoff);
            unsigned long long a01 = ffma2(pack2(c0f[0], c0f[1]), k1p, biasp);
            unsigned long long a23 = ffma2(pack2(c0f[2], c0f[3]), k1p, biasp);
            unsigned long long a45 = ffma2(pack2(c1f[0], c1f[1]), k1p, biasp);
            unsigned long long a67 = ffma2(pack2(c1f[2], c1f[3]), k1p, biasp);
            float x0, x1; unpack2(a01, x0, x1);
            float x2, x3; unpack2(a23, x2, x3);
            float x4, x5; unpack2(a45, x4, x5);
            float x6, x7; unpack2(a67, x6, x7);
            uint32_t e0 = ex2_bf16x2(cvt_bf16x2(x0, x1));
            uint32_t e1 = ex2_bf16x2(cvt_bf16x2(x2, x3));
            uint32_t e2 = ex2_bf16x2(cvt_bf16x2(x4, x5));
            uint32_t e3 = ex2_bf16x2(cvt_bf16x2(x6, x7));
            rs[0] = fadd2(rs[0], pack2r(e0 << 16, e0 & 0xFFFF0000u));
            rs[1] = fadd2(rs[1], pack2r(e1 << 16, e1 & 0xFFFF0000u));
            rs[2] = fadd2(rs[2], pack2r(e2 << 16, e2 & 0xFFFF0000u));
            rs[3] = fadd2(rs[3], pack2r(e3 << 16, e3 & 0xFFFF0000u));
        }
        __syncthreads();
    }

    // ---- per-row accumulation ----
    const int rows[4] = { rbase + g, rbase + 8 + g, rbase + 16 + g, rbase + 24 + g };
    #pragma unroll
    for (int q = 0; q < 4; ++q) {
        float s = unpack_sum(rs[q]);
        s += __shfl_xor_sync(0xffffffffu, s, 1);
        s += __shfl_xor_sync(0xffffffffu, s, 2);
        if ((lane & 3) == 0) atomicAdd(&g_rowsum[rows[q]], s);
    }

    // ---- inline finalize: last CTA reduces all rows ----
    __syncthreads();
    if (tid == 0) {
        __threadfence();
        unsigned int old = atomicAdd(&g_done, 1u);
        smflag = (old == (unsigned int)(gridDim.x * gridDim.y - 1)) ? 1 : 0;
    }
    __syncthreads();
    if (smflag) {
        const float log_nu = -logf((float)M);
        double part = 0.0;
        for (int i = tid; i < N; i += THREADS) {
            float lse = -alpha * g_sqs[i] + log_nu + LN2 * (log2f(g_rowsum[i]) - SHIFT);
            part += (double)(-REGP * lse);
        }
        #pragma unroll
        for (int o = 16; o; o >>= 1) part += __shfl_xor_sync(0xffffffffu, part, o);
        if (lane == 0) atomicAdd(&g_result, part);
        __syncthreads();
        if (tid == 0)
            out[0] = (float)(g_result / (double)N + g_psi_sum / (double)M);
    }
}

extern "C" void kernel_launch(void* const* d_in, const int* in_sizes, int n_in,
                              void* d_out, int out_size) {
    const float* src = (const float*)d_in[0];   // [N, 64]
    const float* tgt = (const float*)d_in[1];   // [M, 64]
    const float* psi = (const float*)d_in[2];   // [M]
    int N = in_sizes[0] / DVAL;
    int M = in_sizes[2];

    k_pre<<<296, 256>>>(src, tgt, psi, N, M);

    dim3 grd(N / BLOCK_ROWS, JSPLIT);           // 16 x 9 = 144 CTAs
    k_main_mma<<<grd, THREADS>>>(psi, (float*)d_out, N, M);
}

// round 7
// speedup vs baseline: 1.4369x; 1.0062x over previous
#include <cuda_runtime.h>
#include <cuda_bf16.h>
#include <cstdint>

#define DVAL 64
#define MAXM 16384
#define MAXN 8192
#define REGP   0.05f
#define LOG2E  1.4426950408889634f
#define LN2    0.6931471805599453f
#define SHIFT  28.0f

#define THREADS 512          // 16 warps
#define BLOCK_ROWS 512       // 32 rows per warp
#define TJ 128               // j-tile
#define JSPLIT 9
#define MAXTILES 15          // ceil(128/9)
#define ONESF 0x3F803F80u    // bf16x2 (1.0, 1.0)

__device__ double g_cost_sum;
__device__ double g_psi_sum;
__device__ double g_result;
__device__ unsigned int g_done;
__device__ float  g_sqt[MAXM];
__device__ float  g_sqs[MAXN];
__device__ float  g_rowsum[MAXN];
__device__ uint32_t g_tgtb[MAXM * DVAL / 2];   // bf16x2 packed
__device__ uint32_t g_srcb[MAXN * DVAL / 2];

// ---------- helpers ----------
static __device__ __forceinline__ uint32_t cvt_bf16x2(float lo, float hi) {
    uint32_t r; asm("cvt.rn.bf16x2.f32 %0, %1, %2;" : "=r"(r) : "f"(hi), "f"(lo)); return r;
}
static __device__ __forceinline__ uint32_t ex2_bf16x2(uint32_t a) {
    uint32_t r; asm("ex2.approx.ftz.bf16x2 %0, %1;" : "=r"(r) : "r"(a)); return r;
}
static __device__ __forceinline__ void mma16816(float* c, const uint32_t* a, uint32_t b0, uint32_t b1) {
    asm("mma.sync.aligned.m16n8k16.row.col.f32.bf16.bf16.f32 "
        "{%0,%1,%2,%3}, {%4,%5,%6,%7}, {%8,%9}, {%0,%1,%2,%3};"
        : "+f"(c[0]), "+f"(c[1]), "+f"(c[2]), "+f"(c[3])
        : "r"(a[0]), "r"(a[1]), "r"(a[2]), "r"(a[3]), "r"(b0), "r"(b1));
}
static __device__ __forceinline__ void ldm_x4(uint32_t* r, uint32_t addr) {
    asm volatile("ldmatrix.sync.aligned.m8n8.x4.shared.b16 {%0,%1,%2,%3}, [%4];"
        : "=r"(r[0]), "=r"(r[1]), "=r"(r[2]), "=r"(r[3]) : "r"(addr));
}
static __device__ __forceinline__ uint32_t smem_u32(const void* p) {
    uint32_t a;
    asm("{ .reg .u64 t; cvta.to.shared.u64 t, %1; cvt.u32.u64 %0, t; }" : "=r"(a) : "l"(p));
    return a;
}
#define CP_ASYNC16(dst, src) \
    asm volatile("cp.async.cg.shared.global [%0], [%1], 16;" :: "r"(dst), "l"(src) : "memory")
#define CP_COMMIT() asm volatile("cp.async.commit_group;" ::: "memory")
#define CP_WAIT0()  asm volatile("cp.async.wait_group 0;" ::: "memory")

// ---------------- kernel 1: convert + reductions + init ----------------
__global__ void k_pre(const float* __restrict__ src, const float* __restrict__ tgt,
                      const float* __restrict__ psi, int N, int M) {
    int gtid = blockIdx.x * blockDim.x + threadIdx.x;
    int nth  = gridDim.x * blockDim.x;
    int lane = threadIdx.x & 31;

    if (gtid == 0) { g_cost_sum = 0.0; g_psi_sum = 0.0; g_result = 0.0; g_done = 0u; }
    for (int i = gtid; i < N; i += nth) g_rowsum[i] = 0.0f;

    const float2* t2 = (const float2*)tgt;
    float cs = 0.0f;
    for (int i = gtid; i < M * 32; i += nth) {
        float2 v = t2[i];
        cs += v.x * v.x + v.y * v.y;
        g_tgtb[i] = cvt_bf16x2(v.x, v.y);
    }
    const float2* s2 = (const float2*)src;
    for (int i = gtid; i < N * 32; i += nth) {
        float2 v = s2[i];
        g_srcb[i] = cvt_bf16x2(v.x, v.y);
    }
    float pp = 0.0f;
    for (int i = gtid; i < M; i += nth) pp += psi[i];
    #pragma unroll
    for (int o = 16; o; o >>= 1) {
        cs += __shfl_xor_sync(0xffffffffu, cs, o);
        pp += __shfl_xor_sync(0xffffffffu, pp, o);
    }
    if (lane == 0) {
        atomicAdd(&g_cost_sum, (double)cs);
        if (pp != 0.0f) atomicAdd(&g_psi_sum, (double)pp);
    }

    // per-row squared norms, 4 lanes per row
    int grp = gtid >> 2, sub = gtid & 3, ngrp = nth >> 2;
    for (int row = grp; row < M + N; row += ngrp) {
        const float4* p = (row < M)
            ? (const float4*)(tgt + (size_t)row * DVAL)
            : (const float4*)(src + (size_t)(row - M) * DVAL);
        float s = 0.0f;
        #pragma unroll
        for (int q = 0; q < 4; ++q) {
            float4 v = p[sub + q * 4];
            s += v.x * v.x + v.y * v.y + v.z * v.z + v.w * v.w;
        }
        s += __shfl_xor_sync(0xffffffffu, s, 1);
        s += __shfl_xor_sync(0xffffffffu, s, 2);
        if (sub == 0) {
            if (row < M) g_sqt[row] = s; else g_sqs[row - M] = s;
        }
    }
}

// ---------------- kernel 2: main HMMA + bf16x2 exp2 + mma-reduction ----------------
__global__ void __launch_bounds__(THREADS, 1)
k_main_mma(const float* __restrict__ psi, float* __restrict__ out, int N, int M) {
    __shared__ char sm[2 * 16384 + MAXTILES * TJ * 4];
    __shared__ int smflag;
    float* sbias = (float*)(sm + 32768);
    const uint32_t smb = smem_u32(sm);

    const int tid  = threadIdx.x;
    const int wid  = tid >> 5;
    const int lane = tid & 31;
    const int g    = lane >> 2;

    const int rbase = blockIdx.x * BLOCK_ROWS + wid * 32;

    const int TT = M / TJ;
    const int tbeg = (blockIdx.y * TT) / JSPLIT;
    const int tend = ((blockIdx.y + 1) * TT) / JSPLIT;
    const int jbase = tbeg * TJ;
    const int jcnt  = (tend - tbeg) * TJ;

    // per-thread cp.async chunk coords
    const int ch0 = tid,       r0 = ch0 >> 3, c0 = ch0 & 7;
    const int ch1 = tid + 512, r1 = ch1 >> 3, c1 = ch1 & 7;
    const uint32_t d0 = (uint32_t)((r0 * 128 + c0 * 16) ^ ((r0 & 7) << 4));
    const uint32_t d1 = (uint32_t)((r1 * 128 + c1 * 16) ^ ((r1 & 7) << 4));
    const char* tgtb_bytes = (const char*)g_tgtb;

    // ---- start tile 0 fill ----
    CP_ASYNC16(smb + d0, tgtb_bytes + (size_t)(jbase + r0) * 128 + c0 * 16);
    CP_ASYNC16(smb + d1, tgtb_bytes + (size_t)(jbase + r1) * 128 + c1 * 16);
    CP_COMMIT();

    const float cn = (float)(g_cost_sum / (double)M);
    const float alpha = 1.0f / (REGP * cn);
    const float k1 = 2.0f * LOG2E * alpha;

    // ---- bias for whole j-range into smem (overlaps cp.async) ----
    for (int jj = tid; jj < jcnt; jj += THREADS) {
        int j = jbase + jj;
        sbias[jj] = LOG2E * (psi[j] * (1.0f / REGP) - alpha * g_sqt[j]) + SHIFT;
    }

    // ---- A fragments from bf16 globals ----
    uint32_t afr[2][4][4];
    {
        const uint32_t* xb = g_srcb + (size_t)rbase * 32;
        #pragma unroll
        for (int t = 0; t < 2; ++t) {
            #pragma unroll
            for (int ks = 0; ks < 4; ++ks) {
                const uint32_t* p = xb + (t * 16 + g) * 32 + ks * 8 + (lane & 3);
                afr[t][ks][0] = p[0];
                afr[t][ks][1] = p[256];
                afr[t][ks][2] = p[4];
                afr[t][ks][3] = p[260];
            }
        }
    }

    // ldmatrix per-lane addresses (s-invariant swizzle)
    const int lr = lane & 7, lq = lane >> 3;
    const uint32_t lmoff0 = (uint32_t)(lr * 128 + ((lq * 16)       ^ (lr << 4)));
    const uint32_t lmoff1 = (uint32_t)(lr * 128 + (((lq + 4) * 16) ^ (lr << 4)));
    const int biasoff = (lane & 3) * 2;

    // f32 row-sum accumulators fed by the reduction MMA
    float acc0[4] = {0.f, 0.f, 0.f, 0.f};   // rows g, g+8
    float acc1[4] = {0.f, 0.f, 0.f, 0.f};   // rows g+16, g+24

    for (int t = tbeg; t < tend; ++t) {
        const int cur = (t - tbeg) & 1, nxt = cur ^ 1;
        const bool more = (t + 1 < tend);

        CP_WAIT0();
        __syncthreads();

        if (more) {
            int j0 = (t + 1) * TJ;
            uint32_t dst = smb + (uint32_t)(nxt * 16384);
            CP_ASYNC16(dst + d0, tgtb_bytes + (size_t)(j0 + r0) * 128 + c0 * 16);
            CP_ASYNC16(dst + d1, tgtb_bytes + (size_t)(j0 + r1) * 128 + c1 * 16);
            CP_COMMIT();
        }

        const uint32_t tadd = smb + (uint32_t)(cur * 16384);
        const float* bb = sbias + (t - tbeg) * TJ;
        #pragma unroll 4
        for (int sp = 0; sp < 8; ++sp) {
            uint32_t eA[4], eB[4];   // bf16x2 exps: A-fragments for reduction mma
            #pragma unroll
            for (int h = 0; h < 2; ++h) {
                const int s = sp * 2 + h;
                float c0f[4] = {0.f, 0.f, 0.f, 0.f};
                float c1f[4] = {0.f, 0.f, 0.f, 0.f};
                uint32_t bA[4], bB[4];
                ldm_x4(bA, tadd + s * 1024 + lmoff0);
                ldm_x4(bB, tadd + s * 1024 + lmoff1);
                mma16816(c0f, afr[0][0], bA[0], bA[1]);
                mma16816(c1f, afr[1][0], bA[0], bA[1]);
                mma16816(c0f, afr[0][1], bA[2], bA[3]);
                mma16816(c1f, afr[1][1], bA[2], bA[3]);
                mma16816(c0f, afr[0][2], bB[0], bB[1]);
                mma16816(c1f, afr[1][2], bB[0], bB[1]);
                mma16816(c0f, afr[0][3], bB[2], bB[3]);
                mma16816(c1f, afr[1][3], bB[2], bB[3]);

                const float2 bp = *(const float2*)(bb + s * 8 + biasoff);
                float x0 = fmaf(c0f[0], k1, bp.x);
                float x1 = fmaf(c0f[1], k1, bp.y);
                float x2 = fmaf(c0f[2], k1, bp.x);
                float x3 = fmaf(c0f[3], k1, bp.y);
                float x4 = fmaf(c1f[0], k1, bp.x);
                float x5 = fmaf(c1f[1], k1, bp.y);
                float x6 = fmaf(c1f[2], k1, bp.x);
                float x7 = fmaf(c1f[3], k1, bp.y);
                eA[h * 2 + 0] = ex2_bf16x2(cvt_bf16x2(x0, x1));   // row g
                eA[h * 2 + 1] = ex2_bf16x2(cvt_bf16x2(x2, x3));   // row g+8
                eB[h * 2 + 0] = ex2_bf16x2(cvt_bf16x2(x4, x5));   // row g+16
                eB[h * 2 + 1] = ex2_bf16x2(cvt_bf16x2(x6, x7));   // row g+24
            }
            // row-sum via tensor pipe: C[m,n] += sum_k E[m,k] * 1
            mma16816(acc0, eA, ONESF, ONESF);
            mma16816(acc1, eB, ONESF, ONESF);
        }
        __syncthreads();
    }

    // ---- per-row accumulation: acc[0]/acc[2] hold full row sums (all lanes equal) ----
    if ((lane & 3) == 0) {
        atomicAdd(&g_rowsum[rbase + g],      acc0[0]);
        atomicAdd(&g_rowsum[rbase + 8 + g],  acc0[2]);
        atomicAdd(&g_rowsum[rbase + 16 + g], acc1[0]);
        atomicAdd(&g_rowsum[rbase + 24 + g], acc1[2]);
    }

    // ---- inline finalize: last CTA reduces all rows ----
    __syncthreads();
    if (tid == 0) {
        __threadfence();
        unsigned int old = atomicAdd(&g_done, 1u);
        smflag = (old == (unsigned int)(gridDim.x * gridDim.y - 1)) ? 1 : 0;
    }
    __syncthreads();
    if (smflag) {
        const float log_nu = -logf((float)M);
        double part = 0.0;
        for (int i = tid; i < N; i += THREADS) {
            float lse = -alpha * g_sqs[i] + log_nu + LN2 * (log2f(g_rowsum[i]) - SHIFT);
            part += (double)(-REGP * lse);
        }
        #pragma unroll
        for (int o = 16; o; o >>= 1) part += __shfl_xor_sync(0xffffffffu, part, o);
        if (lane == 0) atomicAdd(&g_result, part);
        __syncthreads();
        if (tid == 0)
            out[0] = (float)(g_result / (double)N + g_psi_sum / (double)M);
    }
}

extern "C" void kernel_launch(void* const* d_in, const int* in_sizes, int n_in,
                              void* d_out, int out_size) {
    const float* src = (const float*)d_in[0];   // [N, 64]
    const float* tgt = (const float*)d_in[1];   // [M, 64]
    const float* psi = (const float*)d_in[2];   // [M]
    int N = in_sizes[0] / DVAL;
    int M = in_sizes[2];

    k_pre<<<296, 256>>>(src, tgt, psi, N, M);

    dim3 grd(N / BLOCK_ROWS, JSPLIT);           // 16 x 9 = 144 CTAs
    k_main_mma<<<grd, THREADS>>>(psi, (float*)d_out, N, M);
}